// round 7
// baseline (speedup 1.0000x reference)
#include <cuda_runtime.h>
#include <cuda_fp16.h>
#include <mma.h>
#include <math.h>
#include <cstdint>

using namespace nvcuda;

#define N_TOK   8192
#define DMODEL  256
#define NEXP    16
#define NVIEW   3
#define TOPK    4
#define HDIM    1024
#define ASSIGN_TOTAL (NVIEW * N_TOK * TOPK)
#define CAP     ASSIGN_TOTAL
#define TPB     256
#define BM      128
#define NCHUNK  16
#define TPB5    512

#define TILE_ELEMS 16384   /* 256x64 (or 64x256) fp16 per chunk */

/* dynamic SMEM layout (bytes) */
#define XH_OFF  0                        /* X fp16 [128][264]  = 67584 */
#define W_OFF   67584                    /* 3 x 36864 cp.async ring    */
#define SLOT_BYTES 36864
#define H_OFF   178176                   /* H fp16 [128][72]   = 18432 */
#define SCR_OFF 196608                   /* fp32 scr [128][64] = 32768 */
#define SM_TOTAL 229376

/* ------------- static device scratch ------------- */
__device__ __half g_w1[NEXP * NCHUNK * TILE_ELEMS];
__device__ __half g_w2[NEXP * NCHUNK * TILE_ELEMS];
__device__ float g_comb[NVIEW * NEXP * DMODEL];
__device__ float g_kn2[NEXP];
__device__ int   g_cnt[NEXP];
__device__ int2  g_bucket[NEXP * CAP];

__device__ __forceinline__ uint32_t s2u(const void* p) {
    uint32_t a;
    asm("{ .reg .u64 t; cvta.to.shared.u64 t, %1; cvt.u32.u64 %0, t; }" : "=r"(a) : "l"(p));
    return a;
}
__device__ __forceinline__ float gelu_exact(float x) {
    return 0.5f * x * (1.0f + erff(x * 0.70710678118654752f));
}

/* ---------------- kernels 0-1: zero / router prep ------------- */
__global__ void zero_kernel(float* __restrict__ out) {
    int i = blockIdx.x * blockDim.x + threadIdx.x;
    if (i < N_TOK * DMODEL) out[i] = 0.0f;
    if (i < NEXP) g_cnt[i] = 0;
}
__global__ void prep_kernel(const float* __restrict__ rw, const float* __restrict__ ek) {
    int t = threadIdx.x, lane = t & 31, w = t >> 5;
    for (int e = w; e < NEXP; e += 8) {
        float s = 0.f;
        #pragma unroll
        for (int j = 0; j < DMODEL; j += 32) { float x = ek[e * DMODEL + lane + j]; s += x * x; }
        #pragma unroll
        for (int o = 16; o; o >>= 1) s += __shfl_xor_sync(0xffffffffu, s, o);
        if (lane == 0) g_kn2[e] = s;
    }
    for (int i = t; i < NVIEW * NEXP * DMODEL; i += TPB) {
        int e = (i >> 8) & 15, d = i & 255;
        g_comb[i] = 2.0f * ek[e * DMODEL + d] + rw[i];
    }
}

/* ---------------- kernel 2: gate with block-aggregated reservation ------------- */
/* 192 blocks x 512 threads; block handles 128 consecutive (view-uniform) tokens
   over 8 iterations (1 warp-token each).  Local slots via smem atomics; ONE
   global atomicAdd per (block, expert); then coalesced record write-out.      */
#define GBLK 192
#define GIT  8
__global__ __launch_bounds__(TPB5) void gate_kernel(const float* __restrict__ v0,
                                                    const float* __restrict__ v1,
                                                    const float* __restrict__ v2) {
    __shared__ float scomb[NEXP * DMODEL];
    __shared__ float skn2[NEXP];
    __shared__ int   scnt[NEXP];
    __shared__ int   sbase[NEXP];
    __shared__ int2  srec[TPB5];
    __shared__ int   sinfo[TPB5];

    int t = threadIdx.x, wid = t >> 5, lane = t & 31;
    int blk = blockIdx.x;
    int view = (blk * 128) >> 13;            /* uniform per block */
    {
        const float* cb = g_comb + view * NEXP * DMODEL;
        for (int i = t; i < NEXP * DMODEL; i += TPB5) scomb[i] = cb[i];
        if (t < NEXP) { skn2[t] = g_kn2[t]; scnt[t] = 0; }
    }
    __syncthreads();

    const float* vbase = (view == 0 ? v0 : (view == 1 ? v1 : v2));

    #pragma unroll 1
    for (int it = 0; it < GIT; it++) {
        int wg  = blk * 128 + it * 16 + wid;
        int tok = wg & (N_TOK - 1);
        const float* vp = vbase + (size_t)tok * DMODEL;
        float xr[8];
        #pragma unroll
        for (int j = 0; j < 8; j++) xr[j] = vp[lane + 32 * j];
        float lg[NEXP];
        #pragma unroll
        for (int e = 0; e < NEXP; e++) {
            float p = 0.f;
            #pragma unroll
            for (int j = 0; j < 8; j++) p += xr[j] * scomb[e * DMODEL + lane + 32 * j];
            #pragma unroll
            for (int o = 16; o; o >>= 1) p += __shfl_xor_sync(0xffffffffu, p, o);
            lg[e] = p - skn2[e];
        }
        if (lane == 0) {
            float tv[TOPK]; int ti[TOPK]; unsigned used = 0;
            #pragma unroll
            for (int k = 0; k < TOPK; k++) {
                float best = -3.0e38f; int bi = 0;
                #pragma unroll
                for (int e = 0; e < NEXP; e++)
                    if (!((used >> e) & 1u) && lg[e] > best) { best = lg[e]; bi = e; }
                used |= 1u << bi; tv[k] = best; ti[k] = bi;
            }
            float mx = tv[0], ex[TOPK], s = 0.f;
            #pragma unroll
            for (int k = 0; k < TOPK; k++) { ex[k] = expf(tv[k] - mx); s += ex[k]; }
            float inv = 1.0f / s;
            int pid = (it * 16 + wid) * TOPK;
            #pragma unroll
            for (int k = 0; k < TOPK; k++) {
                int e = ti[k];
                int slot = atomicAdd(&scnt[e], 1);       /* smem atomic */
                srec[pid + k]  = make_int2(wg, __float_as_int(ex[k] * inv));
                sinfo[pid + k] = (slot << 4) | e;
            }
        }
    }
    __syncthreads();
    if (t < NEXP) sbase[t] = atomicAdd(&g_cnt[t], scnt[t]);   /* 192 per counter */
    __syncthreads();
    {
        int info = sinfo[t];
        int e = info & 15, slot = info >> 4;
        g_bucket[(size_t)e * CAP + sbase[e] + slot] = srec[t];
    }
}

/* -------- kernel 3: convert weights to fp16 in MMA-ready [k][n] chunk order ------ */
__global__ __launch_bounds__(TPB) void wprep_kernel(const float* __restrict__ W1,
                                                    const float* __restrict__ W2) {
    int e = blockIdx.x, c = blockIdx.y, z = blockIdx.z, t = threadIdx.x;
    size_t base = (size_t)(e * NCHUNK + c) * TILE_ELEMS;
    if (z == 0) {
        for (int idx = t; idx < TILE_ELEMS; idx += TPB) {
            int k = idx >> 6, n = idx & 63;
            g_w1[base + idx] = __float2half_rn(W1[(size_t)e * 262144 + (size_t)k * 1024 + c * 64 + n]);
        }
    } else {
        for (int idx = t; idx < TILE_ELEMS; idx += TPB) {
            int k = idx >> 8, n = idx & 255;
            g_w2[base + idx] = __float2half_rn(W2[(size_t)e * 262144 + (size_t)(c * 64 + k) * 256 + n]);
        }
    }
}

/* ---------------- kernel 4: fp16 WMMA grouped fused MLP, full-chunk ring -------- */
typedef wmma::fragment<wmma::matrix_a, 16, 16, 16, __half, wmma::row_major> FragA;
typedef wmma::fragment<wmma::matrix_b, 16, 16, 16, __half, wmma::row_major> FragB;
typedef wmma::fragment<wmma::accumulator, 16, 16, 16, float> FragC;

/* phase p (0..31): p even -> W1 chunk p/2 (256k x 64n, pitch 72 halves);
                    p odd  -> W2 chunk p/2 ( 64k x 256n, pitch 264 halves). */
__device__ __forceinline__ void prefetch_phase(
    int p, int t, uint32_t smb, const __half* w1, const __half* w2)
{
    if (p < NCHUNK * 2) {
        int c = p >> 1;
        uint32_t slot = smb + W_OFF + (uint32_t)(p % 3) * SLOT_BYTES;
        if (!(p & 1)) {
            const char* src = (const char*)(w1 + (size_t)c * TILE_ELEMS);
            #pragma unroll
            for (int v = 0; v < 4; v++) {
                int u = t + TPB5 * v;                 /* 0..2047 16B units */
                uint32_t dst = slot + (uint32_t)(u >> 3) * 144 + (uint32_t)(u & 7) * 16;
                asm volatile("cp.async.cg.shared.global [%0], [%1], 16;"
                             :: "r"(dst), "l"(src + (size_t)u * 16) : "memory");
            }
        } else {
            const char* src = (const char*)(w2 + (size_t)c * TILE_ELEMS);
            #pragma unroll
            for (int v = 0; v < 4; v++) {
                int u = t + TPB5 * v;
                uint32_t dst = slot + (uint32_t)(u >> 5) * 528 + (uint32_t)(u & 31) * 16;
                asm volatile("cp.async.cg.shared.global [%0], [%1], 16;"
                             :: "r"(dst), "l"(src + (size_t)u * 16) : "memory");
            }
        }
    }
    asm volatile("cp.async.commit_group;" ::: "memory");
}

#define SP_BEGIN(p) do {                                             \
    asm volatile("cp.async.wait_group 1;" ::: "memory");             \
    __syncthreads();                                                 \
    prefetch_phase((p) + 2, t, smb, w1, w2);                         \
} while (0)

__global__ __launch_bounds__(TPB5, 1)
void mlp_mma(const float* __restrict__ v0, const float* __restrict__ v1,
             const float* __restrict__ v2,
             const float* __restrict__ b1, const float* __restrict__ b2,
             float* __restrict__ out) {
    int e = blockIdx.y;
    int cnt = g_cnt[e];
    int r0 = blockIdx.x * BM;
    if (r0 >= cnt) return;

    extern __shared__ char dyn[];
    uint32_t smb = s2u(dyn);
    __half* Xh  = (__half*)(dyn + XH_OFF);          /* [128][264] */
    __half* Hh  = (__half*)(dyn + H_OFF);           /* [128][72]  */
    float*  scr = (float*)(dyn + SCR_OFF);          /* [128][64]  */

    __shared__ const float* s_ptr[BM];
    __shared__ float        s_gate[BM];
    __shared__ int          s_tok[BM];

    int t = threadIdx.x;
    const __half* w1 = g_w1 + (size_t)e * NCHUNK * TILE_ELEMS;
    const __half* w2 = g_w2 + (size_t)e * NCHUNK * TILE_ELEMS;

    prefetch_phase(0, t, smb, w1, w2);
    prefetch_phase(1, t, smb, w1, w2);

    if (t < BM) {
        int gr = r0 + t;
        if (gr < cnt) {
            int2 rec = g_bucket[(size_t)e * CAP + gr];
            int view = rec.x >> 13, tok = rec.x & (N_TOK - 1);
            s_ptr[t] = (view == 0 ? v0 : (view == 1 ? v1 : v2)) + (size_t)tok * DMODEL;
            s_tok[t] = tok; s_gate[t] = __int_as_float(rec.y);
        } else { s_ptr[t] = v0; s_tok[t] = 0; s_gate[t] = 0.f; }
    }
    __syncthreads();

    /* stage X fp16: thread t -> row t>>2, 64-col quarter t&3 */
    {
        int m = t >> 2, q = t & 3;
        const float4* src = (const float4*)(s_ptr[m] + q * 64);
        uint32_t* dh = (uint32_t*)&Xh[m * 264 + q * 64];
        #pragma unroll
        for (int j = 0; j < 16; j++) {
            float4 f = src[j];
            __half2 a = __floats2half2_rn(f.x, f.y);
            __half2 b = __floats2half2_rn(f.z, f.w);
            dh[2 * j]     = *(uint32_t*)&a;
            dh[2 * j + 1] = *(uint32_t*)&b;
        }
    }

    int wid = t >> 5;
    int wm = wid >> 2, wn = wid & 3;     /* 4x4 warp grid */

    FragC c2[2][4];
    #pragma unroll
    for (int i = 0; i < 2; i++)
        #pragma unroll
        for (int n = 0; n < 4; n++) wmma::fill_fragment(c2[i][n], 0.0f);

    for (int c = 0; c < NCHUNK; c++) {
        FragC c1[2];
        wmma::fill_fragment(c1[0], 0.0f);
        wmma::fill_fragment(c1[1], 0.0f);

        /* ---- GEMM1: C1[128][64] = X @ W1c, one full-chunk phase ---- */
        SP_BEGIN(2 * c);
        {
            const __half* Ws = (const __half*)(dyn + W_OFF + ((2 * c) % 3) * SLOT_BYTES);
            #pragma unroll
            for (int ks = 0; ks < 16; ks++) {
                FragB b;
                wmma::load_matrix_sync(b, Ws + ks * 16 * 72 + wn * 16, 72);
                #pragma unroll
                for (int i = 0; i < 2; i++) {
                    FragA a;
                    wmma::load_matrix_sync(a, Xh + (wm * 32 + i * 16) * 264 + ks * 16, 264);
                    wmma::mma_sync(c1[i], a, b, c1[i]);
                }
            }
        }

        /* ---- bias + gelu -> H fp16 ---- */
        wmma::store_matrix_sync(&scr[(wm * 32) * 64 + wn * 16], c1[0], 64, wmma::mem_row_major);
        wmma::store_matrix_sync(&scr[(wm * 32 + 16) * 64 + wn * 16], c1[1], 64, wmma::mem_row_major);
        __syncthreads();
        {
            int m = t >> 2, q = t & 3;
            const float* bb = b1 + e * HDIM + c * 64 + q * 16;
            uint32_t* dh = (uint32_t*)&Hh[m * 72 + q * 16];
            #pragma unroll
            for (int j = 0; j < 8; j++) {
                float g0 = gelu_exact(scr[m * 64 + q * 16 + 2 * j]     + __ldg(bb + 2 * j));
                float g1 = gelu_exact(scr[m * 64 + q * 16 + 2 * j + 1] + __ldg(bb + 2 * j + 1));
                __half2 hp = __floats2half2_rn(g0, g1);
                dh[j] = *(uint32_t*)&hp;
            }
        }

        /* ---- GEMM2: C2[128][256] += H @ W2c, one full-chunk phase ---- */
        SP_BEGIN(2 * c + 1);          /* sync also publishes Hh */
        {
            const __half* Ws = (const __half*)(dyn + W_OFF + ((2 * c + 1) % 3) * SLOT_BYTES);
            #pragma unroll
            for (int ks = 0; ks < 4; ks++) {
                FragB b[4];
                #pragma unroll
                for (int nf = 0; nf < 4; nf++)
                    wmma::load_matrix_sync(b[nf], Ws + ks * 16 * 264 + wn * 64 + nf * 16, 264);
                #pragma unroll
                for (int i = 0; i < 2; i++) {
                    FragA a;
                    wmma::load_matrix_sync(a, Hh + (wm * 32 + i * 16) * 72 + ks * 16, 72);
                    #pragma unroll
                    for (int nf = 0; nf < 4; nf++)
                        wmma::mma_sync(c2[i][nf], a, b[nf], c2[i][nf]);
                }
            }
        }
    }

    /* ---- epilogue: C2 -> out (gate, +b2) via scr in 4 column-quarters ---- */
    #pragma unroll
    for (int q = 0; q < 4; q++) {
        __syncthreads();
        if (wn == q) {
            #pragma unroll
            for (int i = 0; i < 2; i++)
                #pragma unroll
                for (int nf = 0; nf < 4; nf++)
                    wmma::store_matrix_sync(&scr[(wm * 32 + i * 16) * 64 + nf * 16],
                                            c2[i][nf], 64, wmma::mem_row_major);
        }
        __syncthreads();
        int m = t >> 2, cq = t & 3;
        float g = s_gate[m];
        if (g != 0.f) {
            int tok = s_tok[m];
            int nbase = q * 64 + cq * 16;
            #pragma unroll
            for (int j = 0; j < 16; j++) {
                int n = nbase + j;
                atomicAdd(&out[(size_t)tok * DMODEL + n],
                          g * (scr[m * 64 + cq * 16 + j] + __ldg(&b2[e * DMODEL + n])));
            }
        }
    }
}

/* ---------------- launch ---------------- */
extern "C" void kernel_launch(void* const* d_in, const int* in_sizes, int n_in,
                              void* d_out, int out_size) {
    const float* v0 = (const float*)d_in[0];
    const float* v1 = (const float*)d_in[1];
    const float* v2 = (const float*)d_in[2];
    const float* rw = (const float*)d_in[3];
    const float* ek = (const float*)d_in[4];
    const float* W1 = (const float*)d_in[5];
    const float* b1 = (const float*)d_in[6];
    const float* W2 = (const float*)d_in[7];
    const float* b2 = (const float*)d_in[8];
    float* out = (float*)d_out;

    cudaFuncSetAttribute(mlp_mma, cudaFuncAttributeMaxDynamicSharedMemorySize, SM_TOTAL);

    zero_kernel<<<(N_TOK * DMODEL + TPB - 1) / TPB, TPB>>>(out);
    prep_kernel<<<1, TPB>>>(rw, ek);
    wprep_kernel<<<dim3(NEXP, NCHUNK, 2), TPB>>>(W1, W2);
    gate_kernel<<<GBLK, TPB5>>>(v0, v1, v2);

    dim3 grid(ASSIGN_TOTAL / BM, NEXP);
    mlp_mma<<<grid, TPB5, SM_TOTAL>>>(v0, v1, v2, b1, b2, out);
}

// round 8
// speedup vs baseline: 1.1764x; 1.1764x over previous
#include <cuda_runtime.h>
#include <cuda_fp16.h>
#include <mma.h>
#include <math.h>
#include <cstdint>

using namespace nvcuda;

#define N_TOK   8192
#define DMODEL  256
#define NEXP    16
#define NVIEW   3
#define TOPK    4
#define HDIM    1024
#define ASSIGN_TOTAL (NVIEW * N_TOK * TOPK)
#define CAP     ASSIGN_TOTAL
#define TPB     256
#define BM      64
#define NCHUNK  16
#define TPB4    256
#define TPB5    512

#define TILE_ELEMS 16384   /* 256x64 (or 64x256) fp16 per chunk */

/* dynamic SMEM layout (bytes) — 97280 total, 2 CTAs/SM */
#define XH_OFF  0                        /* X fp16 [64][264]  = 33792 */
#define W_OFF   33792                    /* 2 x 18432 cp.async ring   */
#define SLOT_BYTES 18432
#define H_OFF   70656                    /* H fp16 [64][72]   = 9216  */
#define SCR_OFF 79872                    /* fp32 scr [64][68] = 17408 */
#define SM_TOTAL 97280

/* ------------- static device scratch ------------- */
__device__ __half g_w1[NEXP * NCHUNK * TILE_ELEMS];
__device__ __half g_w2[NEXP * NCHUNK * TILE_ELEMS];
__device__ float g_comb[NVIEW * NEXP * DMODEL];
__device__ float g_kn2[NEXP];
__device__ int   g_cnt[NEXP];
__device__ int2  g_bucket[NEXP * CAP];

__device__ __forceinline__ uint32_t s2u(const void* p) {
    uint32_t a;
    asm("{ .reg .u64 t; cvta.to.shared.u64 t, %1; cvt.u32.u64 %0, t; }" : "=r"(a) : "l"(p));
    return a;
}
__device__ __forceinline__ float gelu_exact(float x) {
    return 0.5f * x * (1.0f + erff(x * 0.70710678118654752f));
}

/* ---------------- kernels 0-1: zero / router prep ------------- */
__global__ void zero_kernel(float* __restrict__ out) {
    int i = blockIdx.x * blockDim.x + threadIdx.x;
    if (i < N_TOK * DMODEL) out[i] = 0.0f;
    if (i < NEXP) g_cnt[i] = 0;
}
__global__ void prep_kernel(const float* __restrict__ rw, const float* __restrict__ ek) {
    int t = threadIdx.x, lane = t & 31, w = t >> 5;
    for (int e = w; e < NEXP; e += 8) {
        float s = 0.f;
        #pragma unroll
        for (int j = 0; j < DMODEL; j += 32) { float x = ek[e * DMODEL + lane + j]; s += x * x; }
        #pragma unroll
        for (int o = 16; o; o >>= 1) s += __shfl_xor_sync(0xffffffffu, s, o);
        if (lane == 0) g_kn2[e] = s;
    }
    for (int i = t; i < NVIEW * NEXP * DMODEL; i += TPB) {
        int e = (i >> 8) & 15, d = i & 255;
        g_comb[i] = 2.0f * ek[e * DMODEL + d] + rw[i];
    }
}

/* ---------------- kernel 2: gate with block-aggregated reservation (proven) ---- */
#define GBLK 192
#define GIT  8
__global__ __launch_bounds__(TPB5) void gate_kernel(const float* __restrict__ v0,
                                                    const float* __restrict__ v1,
                                                    const float* __restrict__ v2) {
    __shared__ float scomb[NEXP * DMODEL];
    __shared__ float skn2[NEXP];
    __shared__ int   scnt[NEXP];
    __shared__ int   sbase[NEXP];
    __shared__ int2  srec[TPB5];
    __shared__ int   sinfo[TPB5];

    int t = threadIdx.x, wid = t >> 5, lane = t & 31;
    int blk = blockIdx.x;
    int view = (blk * 128) >> 13;
    {
        const float* cb = g_comb + view * NEXP * DMODEL;
        for (int i = t; i < NEXP * DMODEL; i += TPB5) scomb[i] = cb[i];
        if (t < NEXP) { skn2[t] = g_kn2[t]; scnt[t] = 0; }
    }
    __syncthreads();

    const float* vbase = (view == 0 ? v0 : (view == 1 ? v1 : v2));

    #pragma unroll 1
    for (int it = 0; it < GIT; it++) {
        int wg  = blk * 128 + it * 16 + wid;
        int tok = wg & (N_TOK - 1);
        const float* vp = vbase + (size_t)tok * DMODEL;
        float xr[8];
        #pragma unroll
        for (int j = 0; j < 8; j++) xr[j] = vp[lane + 32 * j];
        float lg[NEXP];
        #pragma unroll
        for (int e = 0; e < NEXP; e++) {
            float p = 0.f;
            #pragma unroll
            for (int j = 0; j < 8; j++) p += xr[j] * scomb[e * DMODEL + lane + 32 * j];
            #pragma unroll
            for (int o = 16; o; o >>= 1) p += __shfl_xor_sync(0xffffffffu, p, o);
            lg[e] = p - skn2[e];
        }
        if (lane == 0) {
            float tv[TOPK]; int ti[TOPK]; unsigned used = 0;
            #pragma unroll
            for (int k = 0; k < TOPK; k++) {
                float best = -3.0e38f; int bi = 0;
                #pragma unroll
                for (int e = 0; e < NEXP; e++)
                    if (!((used >> e) & 1u) && lg[e] > best) { best = lg[e]; bi = e; }
                used |= 1u << bi; tv[k] = best; ti[k] = bi;
            }
            float mx = tv[0], ex[TOPK], s = 0.f;
            #pragma unroll
            for (int k = 0; k < TOPK; k++) { ex[k] = expf(tv[k] - mx); s += ex[k]; }
            float inv = 1.0f / s;
            int pid = (it * 16 + wid) * TOPK;
            #pragma unroll
            for (int k = 0; k < TOPK; k++) {
                int e = ti[k];
                int slot = atomicAdd(&scnt[e], 1);
                srec[pid + k]  = make_int2(wg, __float_as_int(ex[k] * inv));
                sinfo[pid + k] = (slot << 4) | e;
            }
        }
    }
    __syncthreads();
    if (t < NEXP) sbase[t] = atomicAdd(&g_cnt[t], scnt[t]);
    __syncthreads();
    {
        int info = sinfo[t];
        int e = info & 15, slot = info >> 4;
        g_bucket[(size_t)e * CAP + sbase[e] + slot] = srec[t];
    }
}

/* -------- kernel 3: convert weights to fp16 in MMA-ready [k][n] chunk order ------ */
__global__ __launch_bounds__(TPB) void wprep_kernel(const float* __restrict__ W1,
                                                    const float* __restrict__ W2) {
    int e = blockIdx.x, c = blockIdx.y, z = blockIdx.z, t = threadIdx.x;
    size_t base = (size_t)(e * NCHUNK + c) * TILE_ELEMS;
    if (z == 0) {
        for (int idx = t; idx < TILE_ELEMS; idx += TPB) {
            int k = idx >> 6, n = idx & 63;
            g_w1[base + idx] = __float2half_rn(W1[(size_t)e * 262144 + (size_t)k * 1024 + c * 64 + n]);
        }
    } else {
        for (int idx = t; idx < TILE_ELEMS; idx += TPB) {
            int k = idx >> 8, n = idx & 255;
            g_w2[base + idx] = __float2half_rn(W2[(size_t)e * 262144 + (size_t)(c * 64 + k) * 256 + n]);
        }
    }
}

/* ------- kernel 4: fp16 WMMA grouped MLP, BM=64, 256 thr, 2 CTAs/SM ------- */
typedef wmma::fragment<wmma::matrix_a, 16, 16, 16, __half, wmma::row_major> FragA;
typedef wmma::fragment<wmma::matrix_b, 16, 16, 16, __half, wmma::row_major> FragB;
typedef wmma::fragment<wmma::accumulator, 16, 16, 16, float> FragC;

/* sub-phase p (0..63): chunk c = p>>2, sub = p&3.
   sub 0/1: W1 k-half sub     (128k x 64n,  pitch 72 halves / 144 B)
   sub 2/3: W2 k-half (sub-2) ( 32k x 256n, pitch 264 halves / 528 B)   */
__device__ __forceinline__ void prefetch_phase(
    int p, int t, uint32_t smb, const __half* w1, const __half* w2)
{
    if (p < NCHUNK * 4) {
        int c = p >> 2, sub = p & 3;
        uint32_t slot = smb + W_OFF + (uint32_t)(p & 1) * SLOT_BYTES;
        if (sub < 2) {
            const char* src = (const char*)(w1 + ((size_t)c * 256 + sub * 128) * 64);
            #pragma unroll
            for (int v = 0; v < 4; v++) {
                int u = t + TPB4 * v;                 /* 0..1023 16B units */
                uint32_t dst = slot + (uint32_t)(u >> 3) * 144 + (uint32_t)(u & 7) * 16;
                asm volatile("cp.async.cg.shared.global [%0], [%1], 16;"
                             :: "r"(dst), "l"(src + (size_t)u * 16) : "memory");
            }
        } else {
            const char* src = (const char*)(w2 + ((size_t)c * 64 + (sub - 2) * 32) * 256);
            #pragma unroll
            for (int v = 0; v < 4; v++) {
                int u = t + TPB4 * v;
                uint32_t dst = slot + (uint32_t)(u >> 5) * 528 + (uint32_t)(u & 31) * 16;
                asm volatile("cp.async.cg.shared.global [%0], [%1], 16;"
                             :: "r"(dst), "l"(src + (size_t)u * 16) : "memory");
            }
        }
    }
    asm volatile("cp.async.commit_group;" ::: "memory");
}

/* double buffer: wait for phase p (all outstanding), sync, prefetch p+1 */
#define SP_BEGIN(p) do {                                             \
    asm volatile("cp.async.wait_group 0;" ::: "memory");             \
    __syncthreads();                                                 \
    prefetch_phase((p) + 1, t, smb, w1, w2);                         \
} while (0)

__global__ __launch_bounds__(TPB4, 2)
void mlp_mma(const float* __restrict__ v0, const float* __restrict__ v1,
             const float* __restrict__ v2,
             const float* __restrict__ b1, const float* __restrict__ b2,
             float* __restrict__ out) {
    int e = blockIdx.y;
    int cnt = g_cnt[e];
    int r0 = blockIdx.x * BM;
    if (r0 >= cnt) return;

    extern __shared__ char dyn[];
    uint32_t smb = s2u(dyn);
    __half* Xh  = (__half*)(dyn + XH_OFF);          /* [64][264] */
    __half* Hh  = (__half*)(dyn + H_OFF);           /* [64][72]  */
    float*  scr = (float*)(dyn + SCR_OFF);          /* [64][68]  */

    __shared__ const float* s_ptr[BM];
    __shared__ float        s_gate[BM];
    __shared__ int          s_tok[BM];

    int t = threadIdx.x;
    const __half* w1 = g_w1 + (size_t)e * NCHUNK * TILE_ELEMS;
    const __half* w2 = g_w2 + (size_t)e * NCHUNK * TILE_ELEMS;

    prefetch_phase(0, t, smb, w1, w2);

    if (t < BM) {
        int gr = r0 + t;
        if (gr < cnt) {
            int2 rec = g_bucket[(size_t)e * CAP + gr];
            int view = rec.x >> 13, tok = rec.x & (N_TOK - 1);
            s_ptr[t] = (view == 0 ? v0 : (view == 1 ? v1 : v2)) + (size_t)tok * DMODEL;
            s_tok[t] = tok; s_gate[t] = __int_as_float(rec.y);
        } else { s_ptr[t] = v0; s_tok[t] = 0; s_gate[t] = 0.f; }
    }
    __syncthreads();

    /* stage X fp16: thread t -> row t>>2 (0..63), 64-col quarter t&3 */
    {
        int m = t >> 2, q = t & 3;
        const float4* src = (const float4*)(s_ptr[m] + q * 64);
        uint32_t* dh = (uint32_t*)&Xh[m * 264 + q * 64];
        #pragma unroll
        for (int j = 0; j < 16; j++) {
            float4 f = src[j];
            __half2 a = __floats2half2_rn(f.x, f.y);
            __half2 b = __floats2half2_rn(f.z, f.w);
            dh[2 * j]     = *(uint32_t*)&a;
            dh[2 * j + 1] = *(uint32_t*)&b;
        }
    }

    int wid = t >> 5;
    int wm = wid >> 2, wn = wid & 3;     /* 2x4 warp grid */

    FragC c2[2][4];
    #pragma unroll
    for (int i = 0; i < 2; i++)
        #pragma unroll
        for (int n = 0; n < 4; n++) wmma::fill_fragment(c2[i][n], 0.0f);

    for (int c = 0; c < NCHUNK; c++) {
        int pb = c * 4;
        FragC c1[2];
        wmma::fill_fragment(c1[0], 0.0f);
        wmma::fill_fragment(c1[1], 0.0f);

        /* ---- GEMM1: C1[64][64] = X @ W1c, K=256 in 2 halves ---- */
        #pragma unroll
        for (int h = 0; h < 2; h++) {
            SP_BEGIN(pb + h);
            const __half* Ws = (const __half*)(dyn + W_OFF + ((pb + h) & 1) * SLOT_BYTES);
            #pragma unroll
            for (int ks = 0; ks < 8; ks++) {
                FragB b;
                wmma::load_matrix_sync(b, Ws + ks * 16 * 72 + wn * 16, 72);
                #pragma unroll
                for (int i = 0; i < 2; i++) {
                    FragA a;
                    wmma::load_matrix_sync(a, Xh + (wm * 32 + i * 16) * 264 + h * 128 + ks * 16, 264);
                    wmma::mma_sync(c1[i], a, b, c1[i]);
                }
            }
        }

        /* ---- bias + gelu -> H fp16 ---- */
        wmma::store_matrix_sync(&scr[(wm * 32) * 68 + wn * 16], c1[0], 68, wmma::mem_row_major);
        wmma::store_matrix_sync(&scr[(wm * 32 + 16) * 68 + wn * 16], c1[1], 68, wmma::mem_row_major);
        __syncthreads();
        {
            int m = t >> 2, q = t & 3;
            const float* bb = b1 + e * HDIM + c * 64 + q * 16;
            uint32_t* dh = (uint32_t*)&Hh[m * 72 + q * 16];
            #pragma unroll
            for (int j = 0; j < 8; j++) {
                float g0 = gelu_exact(scr[m * 68 + q * 16 + 2 * j]     + __ldg(bb + 2 * j));
                float g1 = gelu_exact(scr[m * 68 + q * 16 + 2 * j + 1] + __ldg(bb + 2 * j + 1));
                __half2 hp = __floats2half2_rn(g0, g1);
                dh[j] = *(uint32_t*)&hp;
            }
        }

        /* ---- GEMM2: C2[64][256] += H @ W2c, K=64 in 2 halves ---- */
        #pragma unroll
        for (int h = 0; h < 2; h++) {
            SP_BEGIN(pb + 2 + h);        /* sync also publishes Hh */
            const __half* Ws = (const __half*)(dyn + W_OFF + ((pb + 2 + h) & 1) * SLOT_BYTES);
            #pragma unroll
            for (int ks = 0; ks < 2; ks++) {
                #pragma unroll
                for (int i = 0; i < 2; i++) {
                    FragA a;
                    wmma::load_matrix_sync(a, Hh + (wm * 32 + i * 16) * 72 + h * 32 + ks * 16, 72);
                    #pragma unroll
                    for (int nf = 0; nf < 4; nf++) {
                        FragB b;
                        wmma::load_matrix_sync(b, Ws + ks * 16 * 264 + wn * 64 + nf * 16, 264);
                        wmma::mma_sync(c2[i][nf], a, b, c2[i][nf]);
                    }
                }
            }
        }
    }

    /* ---- epilogue: C2 -> out (gate, +b2) via scr in 4 column-quarters ---- */
    #pragma unroll
    for (int q = 0; q < 4; q++) {
        __syncthreads();
        if (wn == q) {
            #pragma unroll
            for (int i = 0; i < 2; i++)
                #pragma unroll
                for (int nf = 0; nf < 4; nf++)
                    wmma::store_matrix_sync(&scr[(wm * 32 + i * 16) * 68 + nf * 16],
                                            c2[i][nf], 68, wmma::mem_row_major);
        }
        __syncthreads();
        int m = t >> 2, cq = t & 3;
        float g = s_gate[m];
        if (g != 0.f) {
            int tok = s_tok[m];
            int nbase = q * 64 + cq * 16;
            #pragma unroll
            for (int j = 0; j < 16; j++) {
                int n = nbase + j;
                atomicAdd(&out[(size_t)tok * DMODEL + n],
                          g * (scr[m * 68 + cq * 16 + j] + __ldg(&b2[e * DMODEL + n])));
            }
        }
    }
}

/* ---------------- launch ---------------- */
extern "C" void kernel_launch(void* const* d_in, const int* in_sizes, int n_in,
                              void* d_out, int out_size) {
    const float* v0 = (const float*)d_in[0];
    const float* v1 = (const float*)d_in[1];
    const float* v2 = (const float*)d_in[2];
    const float* rw = (const float*)d_in[3];
    const float* ek = (const float*)d_in[4];
    const float* W1 = (const float*)d_in[5];
    const float* b1 = (const float*)d_in[6];
    const float* W2 = (const float*)d_in[7];
    const float* b2 = (const float*)d_in[8];
    float* out = (float*)d_out;

    cudaFuncSetAttribute(mlp_mma, cudaFuncAttributeMaxDynamicSharedMemorySize, SM_TOTAL);

    zero_kernel<<<(N_TOK * DMODEL + TPB - 1) / TPB, TPB>>>(out);
    prep_kernel<<<1, TPB>>>(rw, ek);
    wprep_kernel<<<dim3(NEXP, NCHUNK, 2), TPB>>>(W1, W2);
    gate_kernel<<<GBLK, TPB5>>>(v0, v1, v2);

    dim3 grid(ASSIGN_TOTAL / BM, NEXP);
    mlp_mma<<<grid, TPB4, SM_TOTAL>>>(v0, v1, v2, b1, b2, out);
}

// round 9
// speedup vs baseline: 1.2132x; 1.0313x over previous
#include <cuda_runtime.h>
#include <cuda_fp16.h>
#include <mma.h>
#include <math.h>
#include <cstdint>

using namespace nvcuda;

#define N_TOK   8192
#define DMODEL  256
#define NEXP    16
#define NVIEW   3
#define TOPK    4
#define HDIM    1024
#define ASSIGN_TOTAL (NVIEW * N_TOK * TOPK)
#define CAP     ASSIGN_TOTAL
#define TPB     256
#define BM      64
#define NCHUNK  16
#define TPB4    256
#define TPB5    512

#define TILE_ELEMS 16384   /* 256x64 (or 64x256) fp16 per chunk */

/* dynamic SMEM layout (bytes) — 97280 total, 2 CTAs/SM */
#define XH_OFF  0                        /* X fp16 [64][264]  = 33792 */
#define W_OFF   33792                    /* 2 x 18432 cp.async ring   */
#define SLOT_BYTES 18432
#define H_OFF   70656                    /* H fp16 [64][72]   = 9216  */
#define SCR_OFF 79872                    /* fp32 scr [64][68] = 17408 */
#define SM_TOTAL 97280

/* aux kernel block ranges */
#define GBLK  192      /* gate blocks      */
#define WPB   512      /* wprep blocks     */
#define ZBLK  64       /* zero-out blocks  */
#define AUXB  (GBLK + WPB + ZBLK)

/* ------------- static device scratch ------------- */
__device__ __half g_w1[NEXP * NCHUNK * TILE_ELEMS];
__device__ __half g_w2[NEXP * NCHUNK * TILE_ELEMS];
__device__ float g_comb[NVIEW * NEXP * DMODEL];
__device__ float g_kn2[NEXP];
__device__ int   g_cnt[NEXP];
__device__ int2  g_bucket[NEXP * CAP];

__device__ __forceinline__ uint32_t s2u(const void* p) {
    uint32_t a;
    asm("{ .reg .u64 t; cvta.to.shared.u64 t, %1; cvt.u32.u64 %0, t; }" : "=r"(a) : "l"(p));
    return a;
}
__device__ __forceinline__ float gelu_exact(float x) {
    return 0.5f * x * (1.0f + erff(x * 0.70710678118654752f));
}

/* ---------------- kernel 0: router prep (+ counter zero) ------------- */
__global__ void prep_kernel(const float* __restrict__ rw, const float* __restrict__ ek) {
    int t = threadIdx.x, lane = t & 31, w = t >> 5;
    if (t < NEXP) g_cnt[t] = 0;
    for (int e = w; e < NEXP; e += 8) {
        float s = 0.f;
        #pragma unroll
        for (int j = 0; j < DMODEL; j += 32) { float x = ek[e * DMODEL + lane + j]; s += x * x; }
        #pragma unroll
        for (int o = 16; o; o >>= 1) s += __shfl_xor_sync(0xffffffffu, s, o);
        if (lane == 0) g_kn2[e] = s;
    }
    for (int i = t; i < NVIEW * NEXP * DMODEL; i += TPB) {
        int e = (i >> 8) & 15, d = i & 255;
        g_comb[i] = 2.0f * ek[e * DMODEL + d] + rw[i];
    }
}

/* ---------------- aux bodies: gate / wprep / zero ------------- */
__device__ void gate_body(int blk, const float* __restrict__ v0,
                          const float* __restrict__ v1, const float* __restrict__ v2) {
    __shared__ float scomb[NEXP * DMODEL];
    __shared__ float skn2[NEXP];
    __shared__ int   scnt[NEXP];
    __shared__ int   sbase[NEXP];
    __shared__ int2  srec[TPB5];
    __shared__ int   sinfo[TPB5];

    int t = threadIdx.x, wid = t >> 5, lane = t & 31;
    int view = (blk * 128) >> 13;            /* uniform per block */
    {
        const float* cb = g_comb + view * NEXP * DMODEL;
        for (int i = t; i < NEXP * DMODEL; i += TPB5) scomb[i] = cb[i];
        if (t < NEXP) { skn2[t] = g_kn2[t]; scnt[t] = 0; }
    }
    __syncthreads();

    const float* vbase = (view == 0 ? v0 : (view == 1 ? v1 : v2));

    #pragma unroll 1
    for (int it = 0; it < 8; it++) {
        int wg  = blk * 128 + it * 16 + wid;
        int tok = wg & (N_TOK - 1);
        const float* vp = vbase + (size_t)tok * DMODEL;
        float xr[8];
        #pragma unroll
        for (int j = 0; j < 8; j++) xr[j] = vp[lane + 32 * j];
        float lg[NEXP];
        #pragma unroll
        for (int e = 0; e < NEXP; e++) {
            float p = 0.f;
            #pragma unroll
            for (int j = 0; j < 8; j++) p += xr[j] * scomb[e * DMODEL + lane + 32 * j];
            #pragma unroll
            for (int o = 16; o; o >>= 1) p += __shfl_xor_sync(0xffffffffu, p, o);
            lg[e] = p - skn2[e];
        }
        if (lane == 0) {
            float tv[TOPK]; int ti[TOPK]; unsigned used = 0;
            #pragma unroll
            for (int k = 0; k < TOPK; k++) {
                float best = -3.0e38f; int bi = 0;
                #pragma unroll
                for (int e = 0; e < NEXP; e++)
                    if (!((used >> e) & 1u) && lg[e] > best) { best = lg[e]; bi = e; }
                used |= 1u << bi; tv[k] = best; ti[k] = bi;
            }
            float mx = tv[0], ex[TOPK], s = 0.f;
            #pragma unroll
            for (int k = 0; k < TOPK; k++) { ex[k] = expf(tv[k] - mx); s += ex[k]; }
            float inv = 1.0f / s;
            int pid = (it * 16 + wid) * TOPK;
            #pragma unroll
            for (int k = 0; k < TOPK; k++) {
                int e = ti[k];
                int slot = atomicAdd(&scnt[e], 1);
                srec[pid + k]  = make_int2(wg, __float_as_int(ex[k] * inv));
                sinfo[pid + k] = (slot << 4) | e;
            }
        }
    }
    __syncthreads();
    if (t < NEXP) sbase[t] = atomicAdd(&g_cnt[t], scnt[t]);
    __syncthreads();
    {
        int info = sinfo[t];
        int e = info & 15, slot = info >> 4;
        g_bucket[(size_t)e * CAP + sbase[e] + slot] = srec[t];
    }
}

__device__ __forceinline__ uint32_t f2h2(float a, float b) {
    __half2 h = __floats2half2_rn(a, b);
    return *(uint32_t*)&h;
}

__device__ void wprep_body(int tile, const float* __restrict__ W1,
                           const float* __restrict__ W2) {
    int t = threadIdx.x;
    int e = tile >> 5, c = (tile >> 1) & 15, z = tile & 1;
    size_t base = (size_t)(e * NCHUNK + c) * TILE_ELEMS;
    if (z == 0) {
        const float* src = W1 + (size_t)e * 262144 + c * 64;
        uint2* dst = (uint2*)(g_w1 + base);
        for (int u = t; u < 4096; u += TPB5) {
            int k = u >> 4, n4 = u & 15;
            float4 f = *(const float4*)(src + (size_t)k * 1024 + n4 * 4);
            dst[u] = make_uint2(f2h2(f.x, f.y), f2h2(f.z, f.w));
        }
    } else {
        const float* src = W2 + (size_t)e * 262144 + (size_t)c * 64 * 256;
        uint2* dst = (uint2*)(g_w2 + base);
        for (int u = t; u < 4096; u += TPB5) {
            int k = u >> 6, n4 = u & 63;
            float4 f = *(const float4*)(src + (size_t)k * 256 + n4 * 4);
            dst[u] = make_uint2(f2h2(f.x, f.y), f2h2(f.z, f.w));
        }
    }
}

__device__ void zero_body(int b, float* __restrict__ out) {
    float4* o4 = (float4*)out;
    int i0 = b * 8192;
    #pragma unroll
    for (int j = 0; j < 16; j++)
        o4[i0 + j * TPB5 + threadIdx.x] = make_float4(0.f, 0.f, 0.f, 0.f);
}

/* ---------------- kernel 1: fused aux (gate || wprep || zero) ---------------- */
__global__ __launch_bounds__(TPB5) void aux_kernel(
    const float* __restrict__ v0, const float* __restrict__ v1,
    const float* __restrict__ v2,
    const float* __restrict__ W1, const float* __restrict__ W2,
    float* __restrict__ out)
{
    int blk = blockIdx.x;
    if (blk < GBLK)            gate_body(blk, v0, v1, v2);
    else if (blk < GBLK + WPB) wprep_body(blk - GBLK, W1, W2);
    else                       zero_body(blk - GBLK - WPB, out);
}

/* ------- kernel 2: fp16 WMMA grouped MLP, BM=64, 256 thr, 2 CTAs/SM (proven) ------- */
typedef wmma::fragment<wmma::matrix_a, 16, 16, 16, __half, wmma::row_major> FragA;
typedef wmma::fragment<wmma::matrix_b, 16, 16, 16, __half, wmma::row_major> FragB;
typedef wmma::fragment<wmma::accumulator, 16, 16, 16, float> FragC;

__device__ __forceinline__ void prefetch_phase(
    int p, int t, uint32_t smb, const __half* w1, const __half* w2)
{
    if (p < NCHUNK * 4) {
        int c = p >> 2, sub = p & 3;
        uint32_t slot = smb + W_OFF + (uint32_t)(p & 1) * SLOT_BYTES;
        if (sub < 2) {
            const char* src = (const char*)(w1 + ((size_t)c * 256 + sub * 128) * 64);
            #pragma unroll
            for (int v = 0; v < 4; v++) {
                int u = t + TPB4 * v;
                uint32_t dst = slot + (uint32_t)(u >> 3) * 144 + (uint32_t)(u & 7) * 16;
                asm volatile("cp.async.cg.shared.global [%0], [%1], 16;"
                             :: "r"(dst), "l"(src + (size_t)u * 16) : "memory");
            }
        } else {
            const char* src = (const char*)(w2 + ((size_t)c * 64 + (sub - 2) * 32) * 256);
            #pragma unroll
            for (int v = 0; v < 4; v++) {
                int u = t + TPB4 * v;
                uint32_t dst = slot + (uint32_t)(u >> 5) * 528 + (uint32_t)(u & 31) * 16;
                asm volatile("cp.async.cg.shared.global [%0], [%1], 16;"
                             :: "r"(dst), "l"(src + (size_t)u * 16) : "memory");
            }
        }
    }
    asm volatile("cp.async.commit_group;" ::: "memory");
}

#define SP_BEGIN(p) do {                                             \
    asm volatile("cp.async.wait_group 0;" ::: "memory");             \
    __syncthreads();                                                 \
    prefetch_phase((p) + 1, t, smb, w1, w2);                         \
} while (0)

__global__ __launch_bounds__(TPB4, 2)
void mlp_mma(const float* __restrict__ v0, const float* __restrict__ v1,
             const float* __restrict__ v2,
             const float* __restrict__ b1, const float* __restrict__ b2,
             float* __restrict__ out) {
    int e = blockIdx.y;
    int cnt = g_cnt[e];
    int r0 = blockIdx.x * BM;
    if (r0 >= cnt) return;

    extern __shared__ char dyn[];
    uint32_t smb = s2u(dyn);
    __half* Xh  = (__half*)(dyn + XH_OFF);
    __half* Hh  = (__half*)(dyn + H_OFF);
    float*  scr = (float*)(dyn + SCR_OFF);

    __shared__ const float* s_ptr[BM];
    __shared__ float        s_gate[BM];
    __shared__ int          s_tok[BM];

    int t = threadIdx.x;
    const __half* w1 = g_w1 + (size_t)e * NCHUNK * TILE_ELEMS;
    const __half* w2 = g_w2 + (size_t)e * NCHUNK * TILE_ELEMS;

    prefetch_phase(0, t, smb, w1, w2);

    if (t < BM) {
        int gr = r0 + t;
        if (gr < cnt) {
            int2 rec = g_bucket[(size_t)e * CAP + gr];
            int view = rec.x >> 13, tok = rec.x & (N_TOK - 1);
            s_ptr[t] = (view == 0 ? v0 : (view == 1 ? v1 : v2)) + (size_t)tok * DMODEL;
            s_tok[t] = tok; s_gate[t] = __int_as_float(rec.y);
        } else { s_ptr[t] = v0; s_tok[t] = 0; s_gate[t] = 0.f; }
    }
    __syncthreads();

    {
        int m = t >> 2, q = t & 3;
        const float4* src = (const float4*)(s_ptr[m] + q * 64);
        uint32_t* dh = (uint32_t*)&Xh[m * 264 + q * 64];
        #pragma unroll
        for (int j = 0; j < 16; j++) {
            float4 f = src[j];
            __half2 a = __floats2half2_rn(f.x, f.y);
            __half2 b = __floats2half2_rn(f.z, f.w);
            dh[2 * j]     = *(uint32_t*)&a;
            dh[2 * j + 1] = *(uint32_t*)&b;
        }
    }

    int wid = t >> 5;
    int wm = wid >> 2, wn = wid & 3;

    FragC c2[2][4];
    #pragma unroll
    for (int i = 0; i < 2; i++)
        #pragma unroll
        for (int n = 0; n < 4; n++) wmma::fill_fragment(c2[i][n], 0.0f);

    for (int c = 0; c < NCHUNK; c++) {
        int pb = c * 4;
        FragC c1[2];
        wmma::fill_fragment(c1[0], 0.0f);
        wmma::fill_fragment(c1[1], 0.0f);

        #pragma unroll
        for (int h = 0; h < 2; h++) {
            SP_BEGIN(pb + h);
            const __half* Ws = (const __half*)(dyn + W_OFF + ((pb + h) & 1) * SLOT_BYTES);
            #pragma unroll
            for (int ks = 0; ks < 8; ks++) {
                FragB b;
                wmma::load_matrix_sync(b, Ws + ks * 16 * 72 + wn * 16, 72);
                #pragma unroll
                for (int i = 0; i < 2; i++) {
                    FragA a;
                    wmma::load_matrix_sync(a, Xh + (wm * 32 + i * 16) * 264 + h * 128 + ks * 16, 264);
                    wmma::mma_sync(c1[i], a, b, c1[i]);
                }
            }
        }

        wmma::store_matrix_sync(&scr[(wm * 32) * 68 + wn * 16], c1[0], 68, wmma::mem_row_major);
        wmma::store_matrix_sync(&scr[(wm * 32 + 16) * 68 + wn * 16], c1[1], 68, wmma::mem_row_major);
        __syncthreads();
        {
            int m = t >> 2, q = t & 3;
            const float* bb = b1 + e * HDIM + c * 64 + q * 16;
            uint32_t* dh = (uint32_t*)&Hh[m * 72 + q * 16];
            #pragma unroll
            for (int j = 0; j < 8; j++) {
                float g0 = gelu_exact(scr[m * 68 + q * 16 + 2 * j]     + __ldg(bb + 2 * j));
                float g1 = gelu_exact(scr[m * 68 + q * 16 + 2 * j + 1] + __ldg(bb + 2 * j + 1));
                __half2 hp = __floats2half2_rn(g0, g1);
                dh[j] = *(uint32_t*)&hp;
            }
        }

        #pragma unroll
        for (int h = 0; h < 2; h++) {
            SP_BEGIN(pb + 2 + h);
            const __half* Ws = (const __half*)(dyn + W_OFF + ((pb + 2 + h) & 1) * SLOT_BYTES);
            #pragma unroll
            for (int ks = 0; ks < 2; ks++) {
                #pragma unroll
                for (int i = 0; i < 2; i++) {
                    FragA a;
                    wmma::load_matrix_sync(a, Hh + (wm * 32 + i * 16) * 72 + h * 32 + ks * 16, 72);
                    #pragma unroll
                    for (int nf = 0; nf < 4; nf++) {
                        FragB b;
                        wmma::load_matrix_sync(b, Ws + ks * 16 * 264 + wn * 64 + nf * 16, 264);
                        wmma::mma_sync(c2[i][nf], a, b, c2[i][nf]);
                    }
                }
            }
        }
    }

    #pragma unroll
    for (int q = 0; q < 4; q++) {
        __syncthreads();
        if (wn == q) {
            #pragma unroll
            for (int i = 0; i < 2; i++)
                #pragma unroll
                for (int nf = 0; nf < 4; nf++)
                    wmma::store_matrix_sync(&scr[(wm * 32 + i * 16) * 68 + nf * 16],
                                            c2[i][nf], 68, wmma::mem_row_major);
        }
        __syncthreads();
        int m = t >> 2, cq = t & 3;
        float g = s_gate[m];
        if (g != 0.f) {
            int tok = s_tok[m];
            int nbase = q * 64 + cq * 16;
            #pragma unroll
            for (int j = 0; j < 16; j++) {
                int n = nbase + j;
                atomicAdd(&out[(size_t)tok * DMODEL + n],
                          g * (scr[m * 68 + cq * 16 + j] + __ldg(&b2[e * DMODEL + n])));
            }
        }
    }
}

/* ---------------- launch ---------------- */
extern "C" void kernel_launch(void* const* d_in, const int* in_sizes, int n_in,
                              void* d_out, int out_size) {
    const float* v0 = (const float*)d_in[0];
    const float* v1 = (const float*)d_in[1];
    const float* v2 = (const float*)d_in[2];
    const float* rw = (const float*)d_in[3];
    const float* ek = (const float*)d_in[4];
    const float* W1 = (const float*)d_in[5];
    const float* b1 = (const float*)d_in[6];
    const float* W2 = (const float*)d_in[7];
    const float* b2 = (const float*)d_in[8];
    float* out = (float*)d_out;

    cudaFuncSetAttribute(mlp_mma, cudaFuncAttributeMaxDynamicSharedMemorySize, SM_TOTAL);

    prep_kernel<<<1, TPB>>>(rw, ek);
    aux_kernel<<<AUXB, TPB5>>>(v0, v1, v2, W1, W2, out);

    dim3 grid(ASSIGN_TOTAL / BM, NEXP);
    mlp_mma<<<grid, TPB4, SM_TOTAL>>>(v0, v1, v2, b1, b2, out);
}